// round 8
// baseline (speedup 1.0000x reference)
#include <cuda_runtime.h>
#include <math.h>
#include <stdint.h>

#define NN    30000
#define DMAXN 16
#define INF   128
#define HIDF  256

typedef uint32_t u32;

// permutation of k-columns within a 16-chunk: pos = (k&3)*4 + (k>>2)
#define PERM16(k) (((((k) & 3) << 2)) | ((k) >> 2))

// ---------------- tf32 helpers ----------------------------------------------
__device__ __forceinline__ u32 f2tf(float x) {
    u32 r; asm("cvt.rna.tf32.f32 %0, %1;" : "=r"(r) : "f"(x)); return r;
}
// D(16x8) += A(16x8,row) * B(8x8,col)
__device__ __forceinline__ void mma8(float* d, const u32* a, const u32* b) {
    asm volatile("mma.sync.aligned.m16n8k8.row.col.f32.tf32.tf32.f32 "
                 "{%0,%1,%2,%3}, {%4,%5,%6,%7}, {%8,%9}, {%0,%1,%2,%3};"
                 : "+f"(d[0]), "+f"(d[1]), "+f"(d[2]), "+f"(d[3])
                 : "r"(a[0]), "r"(a[1]), "r"(a[2]), "r"(a[3]),
                   "r"(b[0]), "r"(b[1]));
}
__device__ __forceinline__ float sigmoid_f(float x) {
    return __fdividef(1.f, 1.f + __expf(-x));
}
__device__ __forceinline__ float tanh_f(float x) {
    float ax = fabsf(x);
    float e = __expf(-2.f * ax);
    return copysignf(__fdividef(1.f - e, 1.f + e), x);
}

// ---------------- scratch (device globals) -----------------------------------
__device__ u32   d_featq[NN * INF];        // tf32-permuted feat
__device__ u32   d_houtq[NN * HIDF];       // tf32-permuted layer-1 output
__device__ u32   d_h1q[2][NN * INF];       // tf32-permuted h (sorted rows)
__device__ u32   d_h2q[2][NN * HIDF];
__device__ float d_c1[NN * INF];           // fp32 cell state
__device__ float d_c2[NN * HIDF];
__device__ float d_gx1[NN * 4 * INF];      // fp32 x-gates (+biases)
__device__ float d_gx2[NN * 4 * HIDF];
__device__ u32   d_Wih1q[4 * INF * INF];
__device__ u32   d_Whh1q[4 * INF * INF];
__device__ u32   d_Wih2q[4 * HIDF * HIDF];
__device__ u32   d_Whh2q[4 * HIDF * HIDF];
__device__ u32   d_Ws1q[HIDF * INF];
__device__ u32   d_Wn1q[HIDF * INF];
__device__ u32   d_Ws2q[64 * HIDF];
__device__ u32   d_Wn2q[64 * HIDF];
__device__ int   d_perm[NN];
__device__ int   d_rank[NN];
__device__ int   d_cnt[DMAXN + 2];
__device__ int   d_ofs[DMAXN + 2];
__device__ int   d_Kt[DMAXN + 1];

// ---------------- counting sort by degree (descending) ----------------------
__global__ void sort_zero_k() {
    if (threadIdx.x < DMAXN + 2) d_cnt[threadIdx.x] = 0;
}
__global__ void sort_hist_k(const int* __restrict__ deg, int n) {
    int i = blockIdx.x * blockDim.x + threadIdx.x;
    if (i < n) atomicAdd(&d_cnt[deg[i]], 1);
}
__global__ void sort_scan_k() {
    int ofs[DMAXN + 2];
    int run = 0;
    for (int d = DMAXN; d >= 1; --d) { ofs[d] = run; run += d_cnt[d]; }
    for (int d = 1; d <= DMAXN; ++d) d_ofs[d] = ofs[d];
    for (int t = 0; t < DMAXN; ++t) d_Kt[t] = ofs[t + 1] + d_cnt[t + 1];
}
__global__ void sort_scatter_k(const int* __restrict__ deg, int n) {
    int i = blockIdx.x * blockDim.x + threadIdx.x;
    if (i < n) {
        int p = atomicAdd(&d_ofs[deg[i]], 1);
        d_perm[p] = i;
        d_rank[i] = p;
    }
}
__global__ void zero_states_k() {
    const int n1 = NN * INF / 4;
    const int n2 = NN * HIDF / 4;
    float4 z = make_float4(0.f, 0.f, 0.f, 0.f);
    int stride = gridDim.x * blockDim.x;
    for (int i = blockIdx.x * blockDim.x + threadIdx.x; i < n2; i += stride) {
        reinterpret_cast<float4*>(d_c2)[i] = z;
        if (i < n1) reinterpret_cast<float4*>(d_c1)[i] = z;
    }
}

// ---------------- fp32 -> tf32 with k-permuted layout ------------------------
template <int DST>
__global__ void convert_perm_k(const float* __restrict__ src, int total) {
    u32* dst;
    if constexpr (DST == 0) dst = d_featq;
    else if constexpr (DST == 1) dst = d_Wih1q;
    else if constexpr (DST == 2) dst = d_Whh1q;
    else if constexpr (DST == 3) dst = d_Wih2q;
    else if constexpr (DST == 4) dst = d_Whh2q;
    else if constexpr (DST == 5) dst = d_Ws1q;
    else if constexpr (DST == 6) dst = d_Wn1q;
    else if constexpr (DST == 7) dst = d_Ws2q;
    else dst = d_Wn2q;
    int stride = gridDim.x * blockDim.x;
    for (int i = blockIdx.x * blockDim.x + threadIdx.x; i < total; i += stride) {
        const int k = i & 15;
        dst[(i & ~15) | PERM16(k)] = f2tf(src[i]);
    }
}

// ---------------- shared mma tile: warp grid 2(M) x 4(N) ---------------------
// As 128 rows, Bs NFRW*32 rows; one LDS.128 per row fetches both k-slices.
template <int NFRW>
__device__ __forceinline__ void mma_tile(const u32 (*__restrict__ As)[20],
                                         const u32 (*__restrict__ Bs)[20],
                                         float (*acc)[NFRW][4],
                                         int wm, int wn, int q, int tig)
{
    uint4 bv[NFRW];
#pragma unroll
    for (int nf = 0; nf < NFRW; nf++)
        bv[nf] = *(const uint4*)&Bs[wn * (8 * NFRW) + nf * 8 + q][4 * tig];
#pragma unroll
    for (int mf = 0; mf < 4; mf++) {
        const uint4 alo = *(const uint4*)&As[wm * 64 + mf * 16 + q][4 * tig];
        const uint4 ahi = *(const uint4*)&As[wm * 64 + mf * 16 + q + 8][4 * tig];
        const u32 a0[4] = {alo.x, ahi.x, alo.y, ahi.y};
        const u32 a1[4] = {alo.z, ahi.z, alo.w, ahi.w};
#pragma unroll
        for (int nf = 0; nf < NFRW; nf++) {
            const u32 b0[2] = {bv[nf].x, bv[nf].y};
            const u32 b1[2] = {bv[nf].z, bv[nf].w};
            mma8(acc[mf][nf], a0, b0);
            mma8(acc[mf][nf], a1, b1);
        }
    }
}

// ============================================================================
// gx = A @ W^T + (bih+bhh) : A [n,K] tf32perm, W [4K,K] tf32perm, out fp32
// ============================================================================
template <int K, int SRC>
__global__ __launch_bounds__(256, 2)
void mma_gx_k(const float* __restrict__ bih, const float* __restrict__ bhh, int n)
{
    const int r0 = blockIdx.x * 128;
    if (r0 >= n) return;
    const int n0 = blockIdx.y * 128;
    constexpr int NCH = K / 16;
    constexpr int M4 = 4 * K;

    __shared__ u32 As[2][128][20];
    __shared__ u32 Bs[2][128][20];

    const u32* A  = (SRC == 1) ? d_featq : d_houtq;
    const u32* Wq = (SRC == 1) ? d_Wih1q : d_Wih2q;
    float* out    = (SRC == 1) ? d_gx1 : d_gx2;

    const int tid = threadIdx.x;
    const int w = tid >> 5, lane = tid & 31;
    const int q = lane >> 2, tig = lane & 3;
    const int wm = w >> 2, wn = w & 3;

    const int prow = tid >> 2;
    const int c4   = (tid & 3) * 4;
    int ra0 = r0 + prow;      if (ra0 > n - 1) ra0 = n - 1;
    int ra1 = r0 + prow + 64; if (ra1 > n - 1) ra1 = n - 1;
    const u32* pa0 = A + (size_t)ra0 * K;
    const u32* pa1 = A + (size_t)ra1 * K;
    const u32* pb0 = Wq + (size_t)(n0 + prow) * K;
    const u32* pb1 = Wq + (size_t)(n0 + prow + 64) * K;

    float acc[4][4][4];
#pragma unroll
    for (int i = 0; i < 4; i++)
#pragma unroll
        for (int j = 0; j < 4; j++)
#pragma unroll
            for (int c = 0; c < 4; c++) acc[i][j][c] = 0.f;

    uint4 fa0 = *(const uint4*)(pa0 + c4);
    uint4 fa1 = *(const uint4*)(pa1 + c4);
    uint4 fb0 = *(const uint4*)(pb0 + c4);
    uint4 fb1 = *(const uint4*)(pb1 + c4);
    *(uint4*)&As[0][prow][c4]      = fa0;
    *(uint4*)&As[0][prow + 64][c4] = fa1;
    *(uint4*)&Bs[0][prow][c4]      = fb0;
    *(uint4*)&Bs[0][prow + 64][c4] = fb1;

#pragma unroll 1
    for (int cch = 0; cch < NCH; cch++) {
        __syncthreads();
        const int buf = cch & 1;
        const bool more = (cch + 1 < NCH);
        if (more) {
            const int kg = (cch + 1) * 16 + c4;
            fa0 = *(const uint4*)(pa0 + kg);
            fa1 = *(const uint4*)(pa1 + kg);
            fb0 = *(const uint4*)(pb0 + kg);
            fb1 = *(const uint4*)(pb1 + kg);
        }
        mma_tile<4>(As[buf], Bs[buf], acc, wm, wn, q, tig);
        if (more) {
            const int nb = (cch + 1) & 1;
            *(uint4*)&As[nb][prow][c4]      = fa0;
            *(uint4*)&As[nb][prow + 64][c4] = fa1;
            *(uint4*)&Bs[nb][prow][c4]      = fb0;
            *(uint4*)&Bs[nb][prow + 64][c4] = fb1;
        }
    }

    float2 bsum[4];
#pragma unroll
    for (int nf = 0; nf < 4; nf++) {
        const int col = n0 + wn * 32 + nf * 8 + 2 * tig;
        bsum[nf] = make_float2(bih[col] + bhh[col], bih[col + 1] + bhh[col + 1]);
    }
#pragma unroll
    for (int mf = 0; mf < 4; mf++)
#pragma unroll
        for (int half = 0; half < 2; half++) {
            const int r = r0 + wm * 64 + mf * 16 + q + half * 8;
            if (r >= n) continue;
#pragma unroll
            for (int nf = 0; nf < 4; nf++) {
                const int col = n0 + wn * 32 + nf * 8 + 2 * tig;
                *(float2*)(out + (size_t)r * M4 + col) =
                    make_float2(acc[mf][nf][half * 2]     + bsum[nf].x,
                                acc[mf][nf][half * 2 + 1] + bsum[nf].y);
            }
        }
}

// ============================================================================
// Fused LSTM step: gates = h_{t-1} @ Whh^T + gx[nbr] (biases already in gx).
// B rows gate-regrouped: brow -> gate (brow>>3)&3, cell (brow&7)+((brow>>5)<<3)
// so warp (wm,wn) frag nf = gate nf, cells j0 + wn*8 + 2tig.
// ============================================================================
template <int H, int LAYER>
__global__ __launch_bounds__(256, 2)
void mma_lstm_k(const int* __restrict__ nbr_idx, int t, int n)
{
    const int Kt = d_Kt[t];
    const int r0 = blockIdx.x * 128;
    if (r0 >= Kt) return;
    const int j0 = blockIdx.y * 32;
    constexpr int NCH = H / 16;

    __shared__ u32 As[2][128][20];
    __shared__ u32 Bs[2][128][20];
    __shared__ int s_nbr[128];

    const float* gx  = (LAYER == 1) ? d_gx1 : d_gx2;
    const u32* hread = (LAYER == 1) ? d_h1q[t & 1] : d_h2q[t & 1];
    u32*      hwrite = (LAYER == 1) ? d_h1q[(t + 1) & 1] : d_h2q[(t + 1) & 1];
    float*    cst    = (LAYER == 1) ? d_c1 : d_c2;
    const u32* Wq    = (LAYER == 1) ? d_Whh1q : d_Whh2q;

    const int tid = threadIdx.x;
    const int w = tid >> 5, lane = tid & 31;
    const int q = lane >> 2, tig = lane & 3;
    const int wm = w >> 2, wn = w & 3;

    if (tid < 128) {
        int r = r0 + tid; if (r > Kt - 1) r = Kt - 1;
        s_nbr[tid] = nbr_idx[d_perm[r] * DMAXN + t];
    }

    float acc[4][4][4];
#pragma unroll
    for (int i = 0; i < 4; i++)
#pragma unroll
        for (int j = 0; j < 4; j++)
#pragma unroll
            for (int c = 0; c < 4; c++) acc[i][j][c] = 0.f;

    if (t > 0) {   // h_0 == 0 -> GEMM vanishes at t==0
        const int prow = tid >> 2;
        const int c4   = (tid & 3) * 4;
        int ra0 = r0 + prow;      if (ra0 > n - 1) ra0 = n - 1;
        int ra1 = r0 + prow + 64; if (ra1 > n - 1) ra1 = n - 1;
        const u32* pa0 = hread + (size_t)ra0 * H;
        const u32* pa1 = hread + (size_t)ra1 * H;
        const int b0r = prow, b1r = prow + 64;
        const int w0 = ((b0r >> 3) & 3) * H + j0 + (b0r & 7) + ((b0r >> 5) << 3);
        const int w1 = ((b1r >> 3) & 3) * H + j0 + (b1r & 7) + ((b1r >> 5) << 3);
        const u32* pb0 = Wq + (size_t)w0 * H;
        const u32* pb1 = Wq + (size_t)w1 * H;

        uint4 fa0 = *(const uint4*)(pa0 + c4);
        uint4 fa1 = *(const uint4*)(pa1 + c4);
        uint4 fb0 = *(const uint4*)(pb0 + c4);
        uint4 fb1 = *(const uint4*)(pb1 + c4);
        *(uint4*)&As[0][prow][c4]      = fa0;
        *(uint4*)&As[0][prow + 64][c4] = fa1;
        *(uint4*)&Bs[0][prow][c4]      = fb0;
        *(uint4*)&Bs[0][prow + 64][c4] = fb1;

#pragma unroll 1
        for (int cch = 0; cch < NCH; cch++) {
            __syncthreads();
            const int buf = cch & 1;
            const bool more = (cch + 1 < NCH);
            if (more) {
                const int kg = (cch + 1) * 16 + c4;
                fa0 = *(const uint4*)(pa0 + kg);
                fa1 = *(const uint4*)(pa1 + kg);
                fb0 = *(const uint4*)(pb0 + kg);
                fb1 = *(const uint4*)(pb1 + kg);
            }
            mma_tile<4>(As[buf], Bs[buf], acc, wm, wn, q, tig);
            if (more) {
                const int nb = (cch + 1) & 1;
                *(uint4*)&As[nb][prow][c4]      = fa0;
                *(uint4*)&As[nb][prow + 64][c4] = fa1;
                *(uint4*)&Bs[nb][prow][c4]      = fb0;
                *(uint4*)&Bs[nb][prow + 64][c4] = fb1;
            }
        }
    }
    __syncthreads();

    // ---- fused cell update: acc[mf][gate][...] + gx ----
    const int jc = j0 + wn * 8 + 2 * tig;
    const int kperm0 = PERM16(jc & 15);
    const int kperm1 = PERM16((jc & 15) + 1);
#pragma unroll
    for (int mf = 0; mf < 4; mf++)
#pragma unroll
        for (int half = 0; half < 2; half++) {
            const int lr = wm * 64 + mf * 16 + q + half * 8;
            const int r = r0 + lr;
            if (r >= Kt) continue;
            const int nbr = s_nbr[lr];
            const float* gp = gx + (size_t)nbr * (4 * H) + jc;
            const float2 gI = *(const float2*)(gp);
            const float2 gF = *(const float2*)(gp + H);
            const float2 gG = *(const float2*)(gp + 2 * H);
            const float2 gO = *(const float2*)(gp + 3 * H);
            const float2 cold = *(const float2*)(cst + (size_t)r * H + jc);
            float cn[2], hn[2];
#pragma unroll
            for (int b = 0; b < 2; b++) {
                const float gi = acc[mf][0][half * 2 + b] + (b ? gI.y : gI.x);
                const float gf = acc[mf][1][half * 2 + b] + (b ? gF.y : gF.x);
                const float gg = acc[mf][2][half * 2 + b] + (b ? gG.y : gG.x);
                const float go = acc[mf][3][half * 2 + b] + (b ? gO.y : gO.x);
                const float cv = sigmoid_f(gf) * (b ? cold.y : cold.x)
                               + sigmoid_f(gi) * tanh_f(gg);
                cn[b] = cv;
                hn[b] = sigmoid_f(go) * tanh_f(cv);
            }
            *(float2*)(cst + (size_t)r * H + jc) = make_float2(cn[0], cn[1]);
            const size_t hb = (size_t)r * H + (jc & ~15);
            hwrite[hb + kperm0] = f2tf(hn[0]);
            hwrite[hb + kperm1] = f2tf(hn[1]);
        }
}

// ============================================================================
// Fused FC: out = act(A1 @ W1^T + m @ W2^T + b), K = K1+K2 concat.
// LAYER 1 writes tf32-permuted d_houtq (relu); LAYER 2 writes fp32 d_out.
// ============================================================================
template <int K1, int K2, int NOUT, int BLKN, int LAYER>
__global__ __launch_bounds__(256, 2)
void mma_fc_k(const int* __restrict__ deg, const float* __restrict__ bias,
              float* __restrict__ outp, int n)
{
    const int r0 = blockIdx.x * 128;
    if (r0 >= n) return;
    const int n0 = blockIdx.y * BLKN;
    constexpr int NCH = (K1 + K2) / 16;
    constexpr int NFRW = BLKN / 32;

    __shared__ u32 As[2][128][20];
    __shared__ u32 Bs[2][BLKN][20];

    const u32* A1 = (LAYER == 1) ? d_featq : d_houtq;
    const u32* W1 = (LAYER == 1) ? d_Ws1q : d_Ws2q;
    const u32* W2 = (LAYER == 1) ? d_Wn1q : d_Wn2q;

    const int tid = threadIdx.x;
    const int w = tid >> 5, lane = tid & 31;
    const int q = lane >> 2, tig = lane & 3;
    const int wm = w >> 2, wn = w & 3;

    const int prow = tid >> 2;
    const int c4   = (tid & 3) * 4;
    int ra0 = r0 + prow;      if (ra0 > n - 1) ra0 = n - 1;
    int ra1 = r0 + prow + 64; if (ra1 > n - 1) ra1 = n - 1;
    const u32* p1a = A1 + (size_t)ra0 * K1;
    const u32* p1b = A1 + (size_t)ra1 * K1;
    const u32* h0a = (LAYER == 1) ? d_h1q[deg[ra0] & 1] : d_h2q[deg[ra0] & 1];
    const u32* h0b = (LAYER == 1) ? d_h1q[deg[ra1] & 1] : d_h2q[deg[ra1] & 1];
    const u32* p2a = h0a + (size_t)d_rank[ra0] * K2;
    const u32* p2b = h0b + (size_t)d_rank[ra1] * K2;
    const u32* q1a = W1 + (size_t)(n0 + prow) * K1;
    const u32* q2a = W2 + (size_t)(n0 + prow) * K2;
    const u32* q1b = W1 + (size_t)(n0 + ((prow + 64) & (BLKN - 1))) * K1;
    const u32* q2b = W2 + (size_t)(n0 + ((prow + 64) & (BLKN - 1))) * K2;

    float acc[4][NFRW][4];
#pragma unroll
    for (int i = 0; i < 4; i++)
#pragma unroll
        for (int j = 0; j < NFRW; j++)
#pragma unroll
            for (int c = 0; c < 4; c++) acc[i][j][c] = 0.f;

    auto ldc = [&](const u32* pk1, const u32* pk2, int kg) {
        return (kg < K1) ? *(const uint4*)(pk1 + kg)
                         : *(const uint4*)(pk2 + (kg - K1));
    };

    uint4 fa0 = ldc(p1a, p2a, c4);
    uint4 fa1 = ldc(p1b, p2b, c4);
    uint4 fb0 = ldc(q1a, q2a, c4);
    uint4 fb1;
    if (BLKN == 128) fb1 = ldc(q1b, q2b, c4);
    *(uint4*)&As[0][prow][c4]      = fa0;
    *(uint4*)&As[0][prow + 64][c4] = fa1;
    *(uint4*)&Bs[0][prow][c4]      = fb0;
    if (BLKN == 128) *(uint4*)&Bs[0][(prow + 64) & (BLKN - 1)][c4] = fb1;

#pragma unroll 1
    for (int cch = 0; cch < NCH; cch++) {
        __syncthreads();
        const int buf = cch & 1;
        const bool more = (cch + 1 < NCH);
        if (more) {
            const int kg = (cch + 1) * 16 + c4;
            fa0 = ldc(p1a, p2a, kg);
            fa1 = ldc(p1b, p2b, kg);
            fb0 = ldc(q1a, q2a, kg);
            if (BLKN == 128) fb1 = ldc(q1b, q2b, kg);
        }
        mma_tile<NFRW>(As[buf], Bs[buf], acc, wm, wn, q, tig);
        if (more) {
            const int nb = (cch + 1) & 1;
            *(uint4*)&As[nb][prow][c4]      = fa0;
            *(uint4*)&As[nb][prow + 64][c4] = fa1;
            *(uint4*)&Bs[nb][prow][c4]      = fb0;
            if (BLKN == 128) *(uint4*)&Bs[nb][(prow + 64) & (BLKN - 1)][c4] = fb1;
        }
    }

    float2 bv2[NFRW];
#pragma unroll
    for (int nf = 0; nf < NFRW; nf++) {
        const int col = n0 + wn * (8 * NFRW) + nf * 8 + 2 * tig;
        bv2[nf] = make_float2(bias[col], bias[col + 1]);
    }
#pragma unroll
    for (int mf = 0; mf < 4; mf++)
#pragma unroll
        for (int half = 0; half < 2; half++) {
            const int r = r0 + wm * 64 + mf * 16 + q + half * 8;
            if (r >= n) continue;
#pragma unroll
            for (int nf = 0; nf < NFRW; nf++) {
                const int col = n0 + wn * (8 * NFRW) + nf * 8 + 2 * tig;
                float v0 = acc[mf][nf][half * 2]     + bv2[nf].x;
                float v1 = acc[mf][nf][half * 2 + 1] + bv2[nf].y;
                if (LAYER == 1) {
                    v0 = fmaxf(v0, 0.f); v1 = fmaxf(v1, 0.f);
                    const size_t hb = (size_t)r * NOUT + (col & ~15);
                    d_houtq[hb + PERM16(col & 15)]       = f2tf(v0);
                    d_houtq[hb + PERM16((col & 15) + 1)] = f2tf(v1);
                } else {
                    *(float2*)(outp + (size_t)r * NOUT + col) = make_float2(v0, v1);
                }
            }
        }
}

// ---------------- launch ----------------------------------------------------
extern "C" void kernel_launch(void* const* d_in, const int* in_sizes, int n_in,
                              void* d_out, int out_size)
{
    const float* feat    = (const float*)d_in[0];
    const int*   nbr     = (const int*)d_in[1];
    const int*   deg     = (const int*)d_in[2];
    const float* Wih1    = (const float*)d_in[3];
    const float* Whh1    = (const float*)d_in[4];
    const float* bih1    = (const float*)d_in[5];
    const float* bhh1    = (const float*)d_in[6];
    const float* Wself1  = (const float*)d_in[7];
    const float* Wneigh1 = (const float*)d_in[8];
    const float* b1      = (const float*)d_in[9];
    const float* Wih2    = (const float*)d_in[10];
    const float* Whh2    = (const float*)d_in[11];
    const float* bih2    = (const float*)d_in[12];
    const float* bhh2    = (const float*)d_in[13];
    const float* Wself2  = (const float*)d_in[14];
    const float* Wneigh2 = (const float*)d_in[15];
    const float* b2      = (const float*)d_in[16];

    const int n  = in_sizes[2];           // = N
    const int rb = (n + 127) / 128;

    sort_zero_k<<<1, 32>>>();
    sort_hist_k<<<(n + 255) / 256, 256>>>(deg, n);
    sort_scan_k<<<1, 1>>>();
    sort_scatter_k<<<(n + 255) / 256, 256>>>(deg, n);
    zero_states_k<<<4096, 256>>>();

    // pre-convert operands to tf32 with k-permuted layout
    convert_perm_k<0><<<512, 256>>>(feat,    in_sizes[0]);
    convert_perm_k<1><<<128, 256>>>(Wih1,    in_sizes[3]);
    convert_perm_k<2><<<128, 256>>>(Whh1,    in_sizes[4]);
    convert_perm_k<3><<<256, 256>>>(Wih2,    in_sizes[10]);
    convert_perm_k<4><<<256, 256>>>(Whh2,    in_sizes[11]);
    convert_perm_k<5><<<64, 256>>>(Wself1,   in_sizes[7]);
    convert_perm_k<6><<<64, 256>>>(Wneigh1,  in_sizes[8]);
    convert_perm_k<7><<<64, 256>>>(Wself2,   in_sizes[14]);
    convert_perm_k<8><<<64, 256>>>(Wneigh2,  in_sizes[15]);

    // layer 1
    mma_gx_k<128, 1><<<dim3(rb, 4), 256>>>(bih1, bhh1, n);
    for (int t = 0; t < 16; t++)
        mma_lstm_k<128, 1><<<dim3(rb, 4), 256>>>(nbr, t, n);
    mma_fc_k<128, 128, 256, 128, 1><<<dim3(rb, 2), 256>>>(deg, b1, nullptr, n);

    // layer 2
    mma_gx_k<256, 2><<<dim3(rb, 8), 256>>>(bih2, bhh2, n);
    for (int t = 0; t < 16; t++)
        mma_lstm_k<256, 2><<<dim3(rb, 8), 256>>>(nbr, t, n);
    mma_fc_k<256, 256, 64, 64, 2><<<dim3(rb, 1), 256>>>(deg, b2,
                                                        (float*)d_out, n);
}

// round 9
// speedup vs baseline: 1.3981x; 1.3981x over previous
#include <cuda_runtime.h>
#include <math.h>
#include <stdint.h>

#define NN    30000
#define DMAXN 16
#define INF   128
#define HIDF  256

typedef uint32_t u32;

// permutation of k-columns within a 16-chunk: pos = (k&3)*4 + (k>>2)
#define PERM16(k) (((((k) & 3) << 2)) | ((k) >> 2))

// ---------------- tf32 / async helpers ---------------------------------------
__device__ __forceinline__ u32 f2tf(float x) {
    u32 r; asm("cvt.rna.tf32.f32 %0, %1;" : "=r"(r) : "f"(x)); return r;
}
__device__ __forceinline__ void mma8(float* d, const u32* a, const u32* b) {
    asm volatile("mma.sync.aligned.m16n8k8.row.col.f32.tf32.tf32.f32 "
                 "{%0,%1,%2,%3}, {%4,%5,%6,%7}, {%8,%9}, {%0,%1,%2,%3};"
                 : "+f"(d[0]), "+f"(d[1]), "+f"(d[2]), "+f"(d[3])
                 : "r"(a[0]), "r"(a[1]), "r"(a[2]), "r"(a[3]),
                   "r"(b[0]), "r"(b[1]));
}
__device__ __forceinline__ u32 smem_u32(const void* p) {
    return (u32)__cvta_generic_to_shared(p);
}
__device__ __forceinline__ void cpa16(u32 d, const void* s) {
    asm volatile("cp.async.cg.shared.global [%0], [%1], 16;" :: "r"(d), "l"(s));
}
__device__ __forceinline__ void cpa_commit() {
    asm volatile("cp.async.commit_group;");
}
template <int N> __device__ __forceinline__ void cpa_wait() {
    asm volatile("cp.async.wait_group %0;" :: "n"(N));
}
__device__ __forceinline__ float sigmoid_f(float x) {
    return __fdividef(1.f, 1.f + __expf(-x));
}
__device__ __forceinline__ float tanh_f(float x) {
    float ax = fabsf(x);
    float e = __expf(-2.f * ax);
    return copysignf(__fdividef(1.f - e, 1.f + e), x);
}

// ---------------- scratch (device globals) -----------------------------------
__device__ u32   d_featq[NN * INF];
__device__ u32   d_houtq[NN * HIDF];
__device__ u32   d_h1q[2][NN * INF];
__device__ u32   d_h2q[2][NN * HIDF];
__device__ float d_c1[NN * INF];
__device__ float d_c2[NN * HIDF];
__device__ float d_gx1[NN * 4 * INF];
__device__ float d_gx2[NN * 4 * HIDF];
__device__ u32   d_Wih1q[4 * INF * INF];
__device__ u32   d_Whh1q[4 * INF * INF];
__device__ u32   d_Wih2q[4 * HIDF * HIDF];
__device__ u32   d_Whh2q[4 * HIDF * HIDF];
__device__ u32   d_Ws1q[HIDF * INF];
__device__ u32   d_Wn1q[HIDF * INF];
__device__ u32   d_Ws2q[64 * HIDF];
__device__ u32   d_Wn2q[64 * HIDF];
__device__ int   d_perm[NN];
__device__ int   d_rank[NN];
__device__ int   d_cnt[DMAXN + 2];
__device__ int   d_ofs[DMAXN + 2];
__device__ int   d_Kt[DMAXN + 1];

// ---------------- counting sort by degree (descending) ----------------------
__global__ void sort_zero_k() {
    if (threadIdx.x < DMAXN + 2) d_cnt[threadIdx.x] = 0;
}
__global__ void sort_hist_k(const int* __restrict__ deg, int n) {
    int i = blockIdx.x * blockDim.x + threadIdx.x;
    if (i < n) atomicAdd(&d_cnt[deg[i]], 1);
}
__global__ void sort_scan_k() {
    int ofs[DMAXN + 2];
    int run = 0;
    for (int d = DMAXN; d >= 1; --d) { ofs[d] = run; run += d_cnt[d]; }
    for (int d = 1; d <= DMAXN; ++d) d_ofs[d] = ofs[d];
    for (int t = 0; t < DMAXN; ++t) d_Kt[t] = ofs[t + 1] + d_cnt[t + 1];
}
__global__ void sort_scatter_k(const int* __restrict__ deg, int n) {
    int i = blockIdx.x * blockDim.x + threadIdx.x;
    if (i < n) {
        int p = atomicAdd(&d_ofs[deg[i]], 1);
        d_perm[p] = i;
        d_rank[i] = p;
    }
}
__global__ void zero_states_k() {
    const int n1 = NN * INF / 4;
    const int n2 = NN * HIDF / 4;
    float4 z = make_float4(0.f, 0.f, 0.f, 0.f);
    int stride = gridDim.x * blockDim.x;
    for (int i = blockIdx.x * blockDim.x + threadIdx.x; i < n2; i += stride) {
        reinterpret_cast<float4*>(d_c2)[i] = z;
        if (i < n1) reinterpret_cast<float4*>(d_c1)[i] = z;
    }
}

// ---------------- fp32 -> tf32 with k-permuted layout ------------------------
template <int DST>
__global__ void convert_perm_k(const float* __restrict__ src, int total) {
    u32* dst;
    if constexpr (DST == 0) dst = d_featq;
    else if constexpr (DST == 1) dst = d_Wih1q;
    else if constexpr (DST == 2) dst = d_Whh1q;
    else if constexpr (DST == 3) dst = d_Wih2q;
    else if constexpr (DST == 4) dst = d_Whh2q;
    else if constexpr (DST == 5) dst = d_Ws1q;
    else if constexpr (DST == 6) dst = d_Wn1q;
    else if constexpr (DST == 7) dst = d_Ws2q;
    else dst = d_Wn2q;
    int stride = gridDim.x * blockDim.x;
    for (int i = blockIdx.x * blockDim.x + threadIdx.x; i < total; i += stride) {
        const int k = i & 15;
        dst[(i & ~15) | PERM16(k)] = f2tf(src[i]);
    }
}

// ---------------- shared mma tile: warp grid 2(M) x 4(N), stride-16 smem -----
// LDS.128 conflict-free: row parity selects 16-word bank half.
template <int NFRW>
__device__ __forceinline__ void mma_tile(const u32 (*__restrict__ As)[16],
                                         const u32 (*__restrict__ Bs)[16],
                                         float (*acc)[NFRW][4],
                                         int wm, int wn, int q, int tig)
{
    uint4 bv[NFRW];
#pragma unroll
    for (int nf = 0; nf < NFRW; nf++)
        bv[nf] = *(const uint4*)&Bs[wn * (8 * NFRW) + nf * 8 + q][4 * tig];
#pragma unroll
    for (int mf = 0; mf < 4; mf++) {
        const uint4 alo = *(const uint4*)&As[wm * 64 + mf * 16 + q][4 * tig];
        const uint4 ahi = *(const uint4*)&As[wm * 64 + mf * 16 + q + 8][4 * tig];
        const u32 a0[4] = {alo.x, ahi.x, alo.y, ahi.y};
        const u32 a1[4] = {alo.z, ahi.z, alo.w, ahi.w};
#pragma unroll
        for (int nf = 0; nf < NFRW; nf++) {
            const u32 b0[2] = {bv[nf].x, bv[nf].y};
            const u32 b1[2] = {bv[nf].z, bv[nf].w};
            mma8(acc[mf][nf], a0, b0);
            mma8(acc[mf][nf], a1, b1);
        }
    }
}

// ============================================================================
// gx = A @ W^T + (bih+bhh) : A [n,K] tf32perm, W [4K,K] tf32perm, out fp32
// ============================================================================
template <int K, int SRC>
__global__ __launch_bounds__(256, 2)
void mma_gx_k(const float* __restrict__ bih, const float* __restrict__ bhh, int n)
{
    const int r0 = blockIdx.x * 128;
    if (r0 >= n) return;
    const int n0 = blockIdx.y * 128;
    constexpr int NCH = K / 16;
    constexpr int M4 = 4 * K;

    __shared__ u32 As[2][128][16];
    __shared__ u32 Bs[2][128][16];
    constexpr u32 BUFSZ = 128 * 16 * 4;

    const u32* A  = (SRC == 1) ? d_featq : d_houtq;
    const u32* Wq = (SRC == 1) ? d_Wih1q : d_Wih2q;
    float* out    = (SRC == 1) ? d_gx1 : d_gx2;

    const int tid = threadIdx.x;
    const int w = tid >> 5, lane = tid & 31;
    const int q = lane >> 2, tig = lane & 3;
    const int wm = w >> 2, wn = w & 3;

    const int prow = tid >> 2;
    const int c4   = (tid & 3) * 4;
    int ra0 = r0 + prow;      if (ra0 > n - 1) ra0 = n - 1;
    int ra1 = r0 + prow + 64; if (ra1 > n - 1) ra1 = n - 1;
    const u32* pa0 = A + (size_t)ra0 * K;
    const u32* pa1 = A + (size_t)ra1 * K;
    const u32* pb0 = Wq + (size_t)(n0 + prow) * K;
    const u32* pb1 = Wq + (size_t)(n0 + prow + 64) * K;

    const u32 a0s = smem_u32(&As[0][prow][c4]);
    const u32 a1s = a0s + 64 * 16 * 4;
    const u32 b0s = smem_u32(&Bs[0][prow][c4]);
    const u32 b1s = b0s + 64 * 16 * 4;

    float acc[4][4][4];
#pragma unroll
    for (int i = 0; i < 4; i++)
#pragma unroll
        for (int j = 0; j < 4; j++)
#pragma unroll
            for (int c = 0; c < 4; c++) acc[i][j][c] = 0.f;

    auto issue = [&](int chunk, int buf) {
        const int kg = chunk * 16 + c4;
        const u32 off = buf * BUFSZ;
        cpa16(a0s + off, pa0 + kg);
        cpa16(a1s + off, pa1 + kg);
        cpa16(b0s + off, pb0 + kg);
        cpa16(b1s + off, pb1 + kg);
        cpa_commit();
    };
    issue(0, 0);
    if (NCH > 1) issue(1, 1);

#pragma unroll 1
    for (int c = 0; c < NCH; c++) {
        if (c + 1 < NCH) cpa_wait<1>(); else cpa_wait<0>();
        __syncthreads();
        mma_tile<4>(As[c & 1], Bs[c & 1], acc, wm, wn, q, tig);
        if (c + 2 < NCH) {
            __syncthreads();
            issue(c + 2, c & 1);
        }
    }

    float2 bsum[4];
#pragma unroll
    for (int nf = 0; nf < 4; nf++) {
        const int col = n0 + wn * 32 + nf * 8 + 2 * tig;
        bsum[nf] = make_float2(bih[col] + bhh[col], bih[col + 1] + bhh[col + 1]);
    }
#pragma unroll
    for (int mf = 0; mf < 4; mf++)
#pragma unroll
        for (int half = 0; half < 2; half++) {
            const int r = r0 + wm * 64 + mf * 16 + q + half * 8;
            if (r >= n) continue;
#pragma unroll
            for (int nf = 0; nf < 4; nf++) {
                const int col = n0 + wn * 32 + nf * 8 + 2 * tig;
                *(float2*)(out + (size_t)r * M4 + col) =
                    make_float2(acc[mf][nf][half * 2]     + bsum[nf].x,
                                acc[mf][nf][half * 2 + 1] + bsum[nf].y);
            }
        }
}

// ============================================================================
// Fused LSTM step: gates = h_{t-1} @ Whh^T + gx[nbr] (biases folded into gx).
// B rows gate-regrouped: brow -> gate (brow>>3)&3, cell (brow&7)+((brow>>5)<<3)
// ============================================================================
template <int H, int LAYER>
__global__ __launch_bounds__(256, 2)
void mma_lstm_k(const int* __restrict__ nbr_idx, int t, int n)
{
    const int Kt = d_Kt[t];
    const int r0 = blockIdx.x * 128;
    if (r0 >= Kt) return;
    const int j0 = blockIdx.y * 32;
    constexpr int NCH = H / 16;

    __shared__ u32 As[2][128][16];
    __shared__ u32 Bs[2][128][16];
    __shared__ int s_nbr[128];
    constexpr u32 BUFSZ = 128 * 16 * 4;

    const float* gx  = (LAYER == 1) ? d_gx1 : d_gx2;
    const u32* hread = (LAYER == 1) ? d_h1q[t & 1] : d_h2q[t & 1];
    u32*      hwrite = (LAYER == 1) ? d_h1q[(t + 1) & 1] : d_h2q[(t + 1) & 1];
    float*    cst    = (LAYER == 1) ? d_c1 : d_c2;
    const u32* Wq    = (LAYER == 1) ? d_Whh1q : d_Whh2q;

    const int tid = threadIdx.x;
    const int w = tid >> 5, lane = tid & 31;
    const int q = lane >> 2, tig = lane & 3;
    const int wm = w >> 2, wn = w & 3;

    if (tid < 128) {
        int r = r0 + tid; if (r > Kt - 1) r = Kt - 1;
        s_nbr[tid] = nbr_idx[d_perm[r] * DMAXN + t];
    }

    float acc[4][4][4];
#pragma unroll
    for (int i = 0; i < 4; i++)
#pragma unroll
        for (int j = 0; j < 4; j++)
#pragma unroll
            for (int c = 0; c < 4; c++) acc[i][j][c] = 0.f;

    if (t > 0) {   // h_0 == 0 -> GEMM vanishes at t==0
        const int prow = tid >> 2;
        const int c4   = (tid & 3) * 4;
        int ra0 = r0 + prow;      if (ra0 > n - 1) ra0 = n - 1;
        int ra1 = r0 + prow + 64; if (ra1 > n - 1) ra1 = n - 1;
        const u32* pa0 = hread + (size_t)ra0 * H;
        const u32* pa1 = hread + (size_t)ra1 * H;
        const int b0r = prow, b1r = prow + 64;
        const int w0 = ((b0r >> 3) & 3) * H + j0 + (b0r & 7) + ((b0r >> 5) << 3);
        const int w1 = ((b1r >> 3) & 3) * H + j0 + (b1r & 7) + ((b1r >> 5) << 3);
        const u32* pb0 = Wq + (size_t)w0 * H;
        const u32* pb1 = Wq + (size_t)w1 * H;

        const u32 a0s = smem_u32(&As[0][prow][c4]);
        const u32 a1s = a0s + 64 * 16 * 4;
        const u32 b0s = smem_u32(&Bs[0][prow][c4]);
        const u32 b1s = b0s + 64 * 16 * 4;

        auto issue = [&](int chunk, int buf) {
            const int kg = chunk * 16 + c4;
            const u32 off = buf * BUFSZ;
            cpa16(a0s + off, pa0 + kg);
            cpa16(a1s + off, pa1 + kg);
            cpa16(b0s + off, pb0 + kg);
            cpa16(b1s + off, pb1 + kg);
            cpa_commit();
        };
        issue(0, 0);
        if (NCH > 1) issue(1, 1);

#pragma unroll 1
        for (int c = 0; c < NCH; c++) {
            if (c + 1 < NCH) cpa_wait<1>(); else cpa_wait<0>();
            __syncthreads();
            mma_tile<4>(As[c & 1], Bs[c & 1], acc, wm, wn, q, tig);
            if (c + 2 < NCH) {
                __syncthreads();
                issue(c + 2, c & 1);
            }
        }
    }
    __syncthreads();

    // ---- fused cell update: acc[mf][gate][...] + gx ----
    const int jc = j0 + wn * 8 + 2 * tig;
    const int kperm0 = PERM16(jc & 15);
    const int kperm1 = PERM16((jc & 15) + 1);
#pragma unroll
    for (int mf = 0; mf < 4; mf++)
#pragma unroll
        for (int half = 0; half < 2; half++) {
            const int lr = wm * 64 + mf * 16 + q + half * 8;
            const int r = r0 + lr;
            if (r >= Kt) continue;
            const int nbr = s_nbr[lr];
            const float* gp = gx + (size_t)nbr * (4 * H) + jc;
            const float2 gI = *(const float2*)(gp);
            const float2 gF = *(const float2*)(gp + H);
            const float2 gG = *(const float2*)(gp + 2 * H);
            const float2 gO = *(const float2*)(gp + 3 * H);
            const float2 cold = *(const float2*)(cst + (size_t)r * H + jc);
            float cn[2], hn[2];
#pragma unroll
            for (int b = 0; b < 2; b++) {
                const float gi = acc[mf][0][half * 2 + b] + (b ? gI.y : gI.x);
                const float gf = acc[mf][1][half * 2 + b] + (b ? gF.y : gF.x);
                const float gg = acc[mf][2][half * 2 + b] + (b ? gG.y : gG.x);
                const float go = acc[mf][3][half * 2 + b] + (b ? gO.y : gO.x);
                const float cv = sigmoid_f(gf) * (b ? cold.y : cold.x)
                               + sigmoid_f(gi) * tanh_f(gg);
                cn[b] = cv;
                hn[b] = sigmoid_f(go) * tanh_f(cv);
            }
            *(float2*)(cst + (size_t)r * H + jc) = make_float2(cn[0], cn[1]);
            const size_t hb = (size_t)r * H + (jc & ~15);
            hwrite[hb + kperm0] = f2tf(hn[0]);
            hwrite[hb + kperm1] = f2tf(hn[1]);
        }
}

// ============================================================================
// Fused FC: out = act(A1 @ W1^T + m @ W2^T + b), K = K1+K2 concat.
// ============================================================================
template <int K1, int K2, int NOUT, int BLKN, int LAYER>
__global__ __launch_bounds__(256, 2)
void mma_fc_k(const int* __restrict__ deg, const float* __restrict__ bias,
              float* __restrict__ outp, int n)
{
    const int r0 = blockIdx.x * 128;
    if (r0 >= n) return;
    const int n0 = blockIdx.y * BLKN;
    constexpr int NCH = (K1 + K2) / 16;
    constexpr int NFRW = BLKN / 32;

    __shared__ u32 As[2][128][16];
    __shared__ u32 Bs[2][BLKN][16];
    constexpr u32 BUFSZ_A = 128 * 16 * 4;
    constexpr u32 BUFSZ_B = BLKN * 16 * 4;

    const u32* A1 = (LAYER == 1) ? d_featq : d_houtq;
    const u32* W1 = (LAYER == 1) ? d_Ws1q : d_Ws2q;
    const u32* W2 = (LAYER == 1) ? d_Wn1q : d_Wn2q;

    const int tid = threadIdx.x;
    const int w = tid >> 5, lane = tid & 31;
    const int q = lane >> 2, tig = lane & 3;
    const int wm = w >> 2, wn = w & 3;

    const int prow = tid >> 2;
    const int c4   = (tid & 3) * 4;
    int ra0 = r0 + prow;      if (ra0 > n - 1) ra0 = n - 1;
    int ra1 = r0 + prow + 64; if (ra1 > n - 1) ra1 = n - 1;
    const u32* p1a = A1 + (size_t)ra0 * K1;
    const u32* p1b = A1 + (size_t)ra1 * K1;
    const u32* h0a = (LAYER == 1) ? d_h1q[deg[ra0] & 1] : d_h2q[deg[ra0] & 1];
    const u32* h0b = (LAYER == 1) ? d_h1q[deg[ra1] & 1] : d_h2q[deg[ra1] & 1];
    const u32* p2a = h0a + (size_t)d_rank[ra0] * K2;
    const u32* p2b = h0b + (size_t)d_rank[ra1] * K2;
    const u32* q1a = W1 + (size_t)(n0 + prow) * K1;
    const u32* q2a = W2 + (size_t)(n0 + prow) * K2;
    const u32* q1b = W1 + (size_t)(n0 + ((prow + 64) & (BLKN - 1))) * K1;
    const u32* q2b = W2 + (size_t)(n0 + ((prow + 64) & (BLKN - 1))) * K2;

    const u32 a0s = smem_u32(&As[0][prow][c4]);
    const u32 a1s = a0s + 64 * 16 * 4;
    const u32 b0s = smem_u32(&Bs[0][prow & (BLKN - 1)][c4]);
    const u32 b1s = smem_u32(&Bs[0][(prow + 64) & (BLKN - 1)][c4]);

    float acc[4][NFRW][4];
#pragma unroll
    for (int i = 0; i < 4; i++)
#pragma unroll
        for (int j = 0; j < NFRW; j++)
#pragma unroll
            for (int c = 0; c < 4; c++) acc[i][j][c] = 0.f;

    auto gsel = [&](const u32* pk1, const u32* pk2, int kg) -> const u32* {
        return (kg < K1) ? (pk1 + kg) : (pk2 + (kg - K1));
    };
    auto issue = [&](int chunk, int buf) {
        const int kg = chunk * 16 + c4;
        cpa16(a0s + buf * BUFSZ_A, gsel(p1a, p2a, kg));
        cpa16(a1s + buf * BUFSZ_A, gsel(p1b, p2b, kg));
        cpa16(b0s + buf * BUFSZ_B, gsel(q1a, q2a, kg));
        if (BLKN == 128) cpa16(b1s + buf * BUFSZ_B, gsel(q1b, q2b, kg));
        cpa_commit();
    };
    issue(0, 0);
    if (NCH > 1) issue(1, 1);

#pragma unroll 1
    for (int c = 0; c < NCH; c++) {
        if (c + 1 < NCH) cpa_wait<1>(); else cpa_wait<0>();
        __syncthreads();
        mma_tile<NFRW>(As[c & 1], Bs[c & 1], acc, wm, wn, q, tig);
        if (c + 2 < NCH) {
            __syncthreads();
            issue(c + 2, c & 1);
        }
    }

    float2 bv2[NFRW];
#pragma unroll
    for (int nf = 0; nf < NFRW; nf++) {
        const int col = n0 + wn * (8 * NFRW) + nf * 8 + 2 * tig;
        bv2[nf] = make_float2(bias[col], bias[col + 1]);
    }
#pragma unroll
    for (int mf = 0; mf < 4; mf++)
#pragma unroll
        for (int half = 0; half < 2; half++) {
            const int r = r0 + wm * 64 + mf * 16 + q + half * 8;
            if (r >= n) continue;
#pragma unroll
            for (int nf = 0; nf < NFRW; nf++) {
                const int col = n0 + wn * (8 * NFRW) + nf * 8 + 2 * tig;
                float v0 = acc[mf][nf][half * 2]     + bv2[nf].x;
                float v1 = acc[mf][nf][half * 2 + 1] + bv2[nf].y;
                if (LAYER == 1) {
                    v0 = fmaxf(v0, 0.f); v1 = fmaxf(v1, 0.f);
                    const size_t hb = (size_t)r * NOUT + (col & ~15);
                    d_houtq[hb + PERM16(col & 15)]       = f2tf(v0);
                    d_houtq[hb + PERM16((col & 15) + 1)] = f2tf(v1);
                } else {
                    *(float2*)(outp + (size_t)r * NOUT + col) = make_float2(v0, v1);
                }
            }
        }
}

// ---------------- launch ----------------------------------------------------
extern "C" void kernel_launch(void* const* d_in, const int* in_sizes, int n_in,
                              void* d_out, int out_size)
{
    const float* feat    = (const float*)d_in[0];
    const int*   nbr     = (const int*)d_in[1];
    const int*   deg     = (const int*)d_in[2];
    const float* Wih1    = (const float*)d_in[3];
    const float* Whh1    = (const float*)d_in[4];
    const float* bih1    = (const float*)d_in[5];
    const float* bhh1    = (const float*)d_in[6];
    const float* Wself1  = (const float*)d_in[7];
    const float* Wneigh1 = (const float*)d_in[8];
    const float* b1      = (const float*)d_in[9];
    const float* Wih2    = (const float*)d_in[10];
    const float* Whh2    = (const float*)d_in[11];
    const float* bih2    = (const float*)d_in[12];
    const float* bhh2    = (const float*)d_in[13];
    const float* Wself2  = (const float*)d_in[14];
    const float* Wneigh2 = (const float*)d_in[15];
    const float* b2      = (const float*)d_in[16];

    const int n  = in_sizes[2];           // = N
    const int rb = (n + 127) / 128;

    sort_zero_k<<<1, 32>>>();
    sort_hist_k<<<(n + 255) / 256, 256>>>(deg, n);
    sort_scan_k<<<1, 1>>>();
    sort_scatter_k<<<(n + 255) / 256, 256>>>(deg, n);
    zero_states_k<<<4096, 256>>>();

    // pre-convert operands to tf32 with k-permuted layout
    convert_perm_k<0><<<512, 256>>>(feat,    in_sizes[0]);
    convert_perm_k<1><<<128, 256>>>(Wih1,    in_sizes[3]);
    convert_perm_k<2><<<128, 256>>>(Whh1,    in_sizes[4]);
    convert_perm_k<3><<<256, 256>>>(Wih2,    in_sizes[10]);
    convert_perm_k<4><<<256, 256>>>(Whh2,    in_sizes[11]);
    convert_perm_k<5><<<64, 256>>>(Wself1,   in_sizes[7]);
    convert_perm_k<6><<<64, 256>>>(Wneigh1,  in_sizes[8]);
    convert_perm_k<7><<<64, 256>>>(Wself2,   in_sizes[14]);
    convert_perm_k<8><<<64, 256>>>(Wneigh2,  in_sizes[15]);

    // layer 1
    mma_gx_k<128, 1><<<dim3(rb, 4), 256>>>(bih1, bhh1, n);
    for (int t = 0; t < 16; t++)
        mma_lstm_k<128, 1><<<dim3(rb, 4), 256>>>(nbr, t, n);
    mma_fc_k<128, 128, 256, 128, 1><<<dim3(rb, 2), 256>>>(deg, b1, nullptr, n);

    // layer 2
    mma_gx_k<256, 2><<<dim3(rb, 8), 256>>>(bih2, bhh2, n);
    for (int t = 0; t < 16; t++)
        mma_lstm_k<256, 2><<<dim3(rb, 8), 256>>>(nbr, t, n);
    mma_fc_k<256, 256, 64, 64, 2><<<dim3(rb, 1), 256>>>(deg, b2,
                                                        (float*)d_out, n);
}

// round 12
// speedup vs baseline: 1.4098x; 1.0084x over previous
#include <cuda_runtime.h>
#include <math.h>
#include <stdint.h>

#define NN    30000
#define DMAXN 16
#define INF   128
#define HIDF  256

typedef uint32_t u32;

// permutation of k-columns within a 16-chunk: pos = (k&3)*4 + (k>>2)
#define PERM16(k) (((((k) & 3) << 2)) | ((k) >> 2))

// ---------------- tf32 / async helpers ---------------------------------------
__device__ __forceinline__ u32 f2tf(float x) {
    u32 r; asm("cvt.rna.tf32.f32 %0, %1;" : "=r"(r) : "f"(x)); return r;
}
__device__ __forceinline__ void mma8(float* d, const u32* a, const u32* b) {
    asm volatile("mma.sync.aligned.m16n8k8.row.col.f32.tf32.tf32.f32 "
                 "{%0,%1,%2,%3}, {%4,%5,%6,%7}, {%8,%9}, {%0,%1,%2,%3};"
                 : "+f"(d[0]), "+f"(d[1]), "+f"(d[2]), "+f"(d[3])
                 : "r"(a[0]), "r"(a[1]), "r"(a[2]), "r"(a[3]),
                   "r"(b[0]), "r"(b[1]));
}
__device__ __forceinline__ u32 smem_u32(const void* p) {
    return (u32)__cvta_generic_to_shared(p);
}
__device__ __forceinline__ void cpa16(u32 d, const void* s) {
    asm volatile("cp.async.cg.shared.global [%0], [%1], 16;" :: "r"(d), "l"(s));
}
__device__ __forceinline__ void cpa_commit() {
    asm volatile("cp.async.commit_group;");
}
template <int N> __device__ __forceinline__ void cpa_wait() {
    asm volatile("cp.async.wait_group %0;" :: "n"(N));
}
__device__ __forceinline__ float sigmoid_f(float x) {
    return __fdividef(1.f, 1.f + __expf(-x));
}
__device__ __forceinline__ float tanh_f(float x) {
    float ax = fabsf(x);
    float e = __expf(-2.f * ax);
    return copysignf(__fdividef(1.f - e, 1.f + e), x);
}

// ---------------- scratch (device globals) -----------------------------------
__device__ u32   d_featq[NN * INF];
__device__ u32   d_houtq[NN * HIDF];
__device__ u32   d_h1q[2][NN * INF];
__device__ u32   d_h2q[2][NN * HIDF];
__device__ float d_c1[NN * INF];          // written at t=0 before any read
__device__ float d_c2[NN * HIDF];
__device__ float d_gx1[NN * 4 * INF];
__device__ float d_gx2[NN * 4 * HIDF];
__device__ u32   d_Wih1q[4 * INF * INF];
__device__ u32   d_Whh1q[4 * INF * INF];
__device__ u32   d_Wih2q[4 * HIDF * HIDF];
__device__ u32   d_Whh2q[4 * HIDF * HIDF];
__device__ u32   d_Ws1q[HIDF * INF];
__device__ u32   d_Wn1q[HIDF * INF];
__device__ u32   d_Ws2q[64 * HIDF];
__device__ u32   d_Wn2q[64 * HIDF];
__device__ int   d_perm[NN];
__device__ int   d_rank[NN];
__device__ int   d_cnt[DMAXN + 2];
__device__ int   d_ofs[DMAXN + 2];
__device__ int   d_Kt[DMAXN + 1];

// ---------------- counting sort by degree (descending) ----------------------
__global__ void sort_zero_k() {
    if (threadIdx.x < DMAXN + 2) d_cnt[threadIdx.x] = 0;
}
__global__ void sort_hist_k(const int* __restrict__ deg, int n) {
    int i = blockIdx.x * blockDim.x + threadIdx.x;
    if (i < n) atomicAdd(&d_cnt[deg[i]], 1);
}
__global__ void sort_scan_k() {
    int ofs[DMAXN + 2];
    int run = 0;
    for (int d = DMAXN; d >= 1; --d) { ofs[d] = run; run += d_cnt[d]; }
    for (int d = 1; d <= DMAXN; ++d) d_ofs[d] = ofs[d];
    for (int t = 0; t < DMAXN; ++t) d_Kt[t] = ofs[t + 1] + d_cnt[t + 1];
}
__global__ void sort_scatter_k(const int* __restrict__ deg, int n) {
    int i = blockIdx.x * blockDim.x + threadIdx.x;
    if (i < n) {
        int p = atomicAdd(&d_ofs[deg[i]], 1);
        d_perm[p] = i;
        d_rank[i] = p;
    }
}

// ---------------- fp32 -> tf32 (k-permuted), all operands in one kernel ------
__global__ void convert_all_k(const float* s0, int n0, const float* s1, int n1,
                              const float* s2, int n2, const float* s3, int n3,
                              const float* s4, int n4, const float* s5, int n5,
                              const float* s6, int n6, const float* s7, int n7,
                              const float* s8, int n8)
{
    const float* srcs[9] = {s0, s1, s2, s3, s4, s5, s6, s7, s8};
    u32* dsts[9] = {d_featq, d_Wih1q, d_Whh1q, d_Wih2q, d_Whh2q,
                    d_Ws1q, d_Wn1q, d_Ws2q, d_Wn2q};
    int lens[9] = {n0, n1, n2, n3, n4, n5, n6, n7, n8};
    int total = 0;
#pragma unroll
    for (int s = 0; s < 9; s++) total += lens[s];

    const int stride = gridDim.x * blockDim.x;
    for (int g = blockIdx.x * blockDim.x + threadIdx.x; g < total; g += stride) {
        int i = g, s = 0;
#pragma unroll
        for (int j = 0; j < 8; j++)
            if (i >= lens[s]) { i -= lens[s]; s++; }
        const int k = i & 15;
        dsts[s][(i & ~15) | PERM16(k)] = f2tf(srcs[s][i]);
    }
}

// ---------------- shared mma tile: warp grid 2(M) x 4(N), stride-16 smem -----
template <int NFRW>
__device__ __forceinline__ void mma_tile(const u32 (*__restrict__ As)[16],
                                         const u32 (*__restrict__ Bs)[16],
                                         float (*acc)[NFRW][4],
                                         int wm, int wn, int q, int tig)
{
    uint4 bv[NFRW];
#pragma unroll
    for (int nf = 0; nf < NFRW; nf++)
        bv[nf] = *(const uint4*)&Bs[wn * (8 * NFRW) + nf * 8 + q][4 * tig];
#pragma unroll
    for (int mf = 0; mf < 4; mf++) {
        const uint4 alo = *(const uint4*)&As[wm * 64 + mf * 16 + q][4 * tig];
        const uint4 ahi = *(const uint4*)&As[wm * 64 + mf * 16 + q + 8][4 * tig];
        const u32 a0[4] = {alo.x, ahi.x, alo.y, ahi.y};
        const u32 a1[4] = {alo.z, ahi.z, alo.w, ahi.w};
#pragma unroll
        for (int nf = 0; nf < NFRW; nf++) {
            const u32 b0[2] = {bv[nf].x, bv[nf].y};
            const u32 b1[2] = {bv[nf].z, bv[nf].w};
            mma8(acc[mf][nf], a0, b0);
            mma8(acc[mf][nf], a1, b1);
        }
    }
}

// ============================================================================
// gx = A @ W^T + (bih+bhh)
// ============================================================================
template <int K, int SRC>
__global__ __launch_bounds__(256, 2)
void mma_gx_k(const float* __restrict__ bih, const float* __restrict__ bhh, int n)
{
    const int r0 = blockIdx.x * 128;
    if (r0 >= n) return;
    const int n0 = blockIdx.y * 128;
    constexpr int NCH = K / 16;
    constexpr int M4 = 4 * K;

    __shared__ u32 As[4][128][16];
    __shared__ u32 Bs[4][128][16];
    constexpr u32 BUFSZ = 128 * 16 * 4;

    const u32* A  = (SRC == 1) ? d_featq : d_houtq;
    const u32* Wq = (SRC == 1) ? d_Wih1q : d_Wih2q;
    float* out    = (SRC == 1) ? d_gx1 : d_gx2;

    const int tid = threadIdx.x;
    const int w = tid >> 5, lane = tid & 31;
    const int q = lane >> 2, tig = lane & 3;
    const int wm = w >> 2, wn = w & 3;

    const int prow = tid >> 2;
    const int c4   = (tid & 3) * 4;
    int ra0 = r0 + prow;      if (ra0 > n - 1) ra0 = n - 1;
    int ra1 = r0 + prow + 64; if (ra1 > n - 1) ra1 = n - 1;
    const u32* pa0 = A + (size_t)ra0 * K;
    const u32* pa1 = A + (size_t)ra1 * K;
    const u32* pb0 = Wq + (size_t)(n0 + prow) * K;
    const u32* pb1 = Wq + (size_t)(n0 + prow + 64) * K;

    const u32 a0s = smem_u32(&As[0][prow][c4]);
    const u32 a1s = a0s + 64 * 16 * 4;
    const u32 b0s = smem_u32(&Bs[0][prow][c4]);
    const u32 b1s = b0s + 64 * 16 * 4;

    float acc[4][4][4];
#pragma unroll
    for (int i = 0; i < 4; i++)
#pragma unroll
        for (int j = 0; j < 4; j++)
#pragma unroll
            for (int c = 0; c < 4; c++) acc[i][j][c] = 0.f;

    auto issue = [&](int chunk) {
        if (chunk < NCH) {
            const int kg = chunk * 16 + c4;
            const u32 off = (chunk & 3) * BUFSZ;
            cpa16(a0s + off, pa0 + kg);
            cpa16(a1s + off, pa1 + kg);
            cpa16(b0s + off, pb0 + kg);
            cpa16(b1s + off, pb1 + kg);
        }
        cpa_commit();
    };
    issue(0); issue(1); issue(2);

#pragma unroll 1
    for (int c = 0; c < NCH; c++) {
        cpa_wait<2>();
        __syncthreads();
        issue(c + 3);
        mma_tile<4>(As[c & 3], Bs[c & 3], acc, wm, wn, q, tig);
    }

    float2 bsum[4];
#pragma unroll
    for (int nf = 0; nf < 4; nf++) {
        const int col = n0 + wn * 32 + nf * 8 + 2 * tig;
        bsum[nf] = make_float2(bih[col] + bhh[col], bih[col + 1] + bhh[col + 1]);
    }
#pragma unroll
    for (int mf = 0; mf < 4; mf++)
#pragma unroll
        for (int half = 0; half < 2; half++) {
            const int r = r0 + wm * 64 + mf * 16 + q + half * 8;
            if (r >= n) continue;
#pragma unroll
            for (int nf = 0; nf < 4; nf++) {
                const int col = n0 + wn * 32 + nf * 8 + 2 * tig;
                *(float2*)(out + (size_t)r * M4 + col) =
                    make_float2(acc[mf][nf][half * 2]     + bsum[nf].x,
                                acc[mf][nf][half * 2 + 1] + bsum[nf].y);
            }
        }
}

// ============================================================================
// Fused LSTM step: gates = h_{t-1} @ Whh^T + gx[nbr] (biases folded into gx).
// t==0: GEMM skipped AND c_old not read (state needs no init).
// ============================================================================
template <int H, int LAYER>
__global__ __launch_bounds__(256, 2)
void mma_lstm_k(const int* __restrict__ nbr_idx, int t, int n)
{
    const int Kt = d_Kt[t];
    const int r0 = blockIdx.x * 128;
    if (r0 >= Kt) return;
    const int j0 = blockIdx.y * 32;
    constexpr int NCH = H / 16;

    __shared__ u32 As[4][128][16];
    __shared__ u32 Bs[4][128][16];
    __shared__ int s_nbr[128];
    constexpr u32 BUFSZ = 128 * 16 * 4;

    const float* gx  = (LAYER == 1) ? d_gx1 : d_gx2;
    const u32* hread = (LAYER == 1) ? d_h1q[t & 1] : d_h2q[t & 1];
    u32*      hwrite = (LAYER == 1) ? d_h1q[(t + 1) & 1] : d_h2q[(t + 1) & 1];
    float*    cst    = (LAYER == 1) ? d_c1 : d_c2;
    const u32* Wq    = (LAYER == 1) ? d_Whh1q : d_Whh2q;

    const int tid = threadIdx.x;
    const int w = tid >> 5, lane = tid & 31;
    const int q = lane >> 2, tig = lane & 3;
    const int wm = w >> 2, wn = w & 3;

    if (tid < 128) {
        int r = r0 + tid; if (r > Kt - 1) r = Kt - 1;
        s_nbr[tid] = nbr_idx[d_perm[r] * DMAXN + t];
    }

    float acc[4][4][4];
#pragma unroll
    for (int i = 0; i < 4; i++)
#pragma unroll
        for (int j = 0; j < 4; j++)
#pragma unroll
            for (int c = 0; c < 4; c++) acc[i][j][c] = 0.f;

    if (t > 0) {
        const int prow = tid >> 2;
        const int c4   = (tid & 3) * 4;
        int ra0 = r0 + prow;      if (ra0 > n - 1) ra0 = n - 1;
        int ra1 = r0 + prow + 64; if (ra1 > n - 1) ra1 = n - 1;
        const u32* pa0 = hread + (size_t)ra0 * H;
        const u32* pa1 = hread + (size_t)ra1 * H;
        const int b0r = prow, b1r = prow + 64;
        const int w0 = ((b0r >> 3) & 3) * H + j0 + (b0r & 7) + ((b0r >> 5) << 3);
        const int w1 = ((b1r >> 3) & 3) * H + j0 + (b1r & 7) + ((b1r >> 5) << 3);
        const u32* pb0 = Wq + (size_t)w0 * H;
        const u32* pb1 = Wq + (size_t)w1 * H;

        const u32 a0s = smem_u32(&As[0][prow][c4]);
        const u32 a1s = a0s + 64 * 16 * 4;
        const u32 b0s = smem_u32(&Bs[0][prow][c4]);
        const u32 b1s = b0s + 64 * 16 * 4;

        auto issue = [&](int chunk) {
            if (chunk < NCH) {
                const int kg = chunk * 16 + c4;
                const u32 off = (chunk & 3) * BUFSZ;
                cpa16(a0s + off, pa0 + kg);
                cpa16(a1s + off, pa1 + kg);
                cpa16(b0s + off, pb0 + kg);
                cpa16(b1s + off, pb1 + kg);
            }
            cpa_commit();
        };
        issue(0); issue(1); issue(2);

#pragma unroll 1
        for (int c = 0; c < NCH; c++) {
            cpa_wait<2>();
            __syncthreads();
            issue(c + 3);
            mma_tile<4>(As[c & 3], Bs[c & 3], acc, wm, wn, q, tig);
        }
    }
    __syncthreads();

    // ---- fused cell update ----
    const int jc = j0 + wn * 8 + 2 * tig;
    const int kperm0 = PERM16(jc & 15);
    const int kperm1 = PERM16((jc & 15) + 1);
#pragma unroll
    for (int mf = 0; mf < 4; mf++)
#pragma unroll
        for (int half = 0; half < 2; half++) {
            const int lr = wm * 64 + mf * 16 + q + half * 8;
            const int r = r0 + lr;
            if (r >= Kt) continue;
            const int nbr = s_nbr[lr];
            const float* gp = gx + (size_t)nbr * (4 * H) + jc;
            const float2 gI = *(const float2*)(gp);
            const float2 gF = *(const float2*)(gp + H);
            const float2 gG = *(const float2*)(gp + 2 * H);
            const float2 gO = *(const float2*)(gp + 3 * H);
            float2 cold = make_float2(0.f, 0.f);
            if (t > 0) cold = *(const float2*)(cst + (size_t)r * H + jc);
            float cn[2], hn[2];
#pragma unroll
            for (int b = 0; b < 2; b++) {
                const float gi = acc[mf][0][half * 2 + b] + (b ? gI.y : gI.x);
                const float gf = acc[mf][1][half * 2 + b] + (b ? gF.y : gF.x);
                const float gg = acc[mf][2][half * 2 + b] + (b ? gG.y : gG.x);
                const float go = acc[mf][3][half * 2 + b] + (b ? gO.y : gO.x);
                const float cv = sigmoid_f(gf) * (b ? cold.y : cold.x)
                               + sigmoid_f(gi) * tanh_f(gg);
                cn[b] = cv;
                hn[b] = sigmoid_f(go) * tanh_f(cv);
            }
            *(float2*)(cst + (size_t)r * H + jc) = make_float2(cn[0], cn[1]);
            const size_t hb = (size_t)r * H + (jc & ~15);
            hwrite[hb + kperm0] = f2tf(hn[0]);
            hwrite[hb + kperm1] = f2tf(hn[1]);
        }
}

// ============================================================================
// Fused FC: out = act(A1 @ W1^T + m @ W2^T + b), K = K1+K2 concat.
// ============================================================================
template <int K1, int K2, int NOUT, int BLKN, int LAYER>
__global__ __launch_bounds__(256, 2)
void mma_fc_k(const int* __restrict__ deg, const float* __restrict__ bias,
              float* __restrict__ outp, int n)
{
    const int r0 = blockIdx.x * 128;
    if (r0 >= n) return;
    const int n0 = blockIdx.y * BLKN;
    constexpr int NCH = (K1 + K2) / 16;
    constexpr int NFRW = BLKN / 32;

    __shared__ u32 As[4][128][16];
    __shared__ u32 Bs[4][BLKN][16];
    constexpr u32 BUFSZ_A = 128 * 16 * 4;
    constexpr u32 BUFSZ_B = BLKN * 16 * 4;

    const u32* A1 = (LAYER == 1) ? d_featq : d_houtq;
    const u32* W1 = (LAYER == 1) ? d_Ws1q : d_Ws2q;
    const u32* W2 = (LAYER == 1) ? d_Wn1q : d_Wn2q;

    const int tid = threadIdx.x;
    const int w = tid >> 5, lane = tid & 31;
    const int q = lane >> 2, tig = lane & 3;
    const int wm = w >> 2, wn = w & 3;

    const int prow = tid >> 2;
    const int c4   = (tid & 3) * 4;
    int ra0 = r0 + prow;      if (ra0 > n - 1) ra0 = n - 1;
    int ra1 = r0 + prow + 64; if (ra1 > n - 1) ra1 = n - 1;
    const u32* p1a = A1 + (size_t)ra0 * K1;
    const u32* p1b = A1 + (size_t)ra1 * K1;
    const u32* h0a = (LAYER == 1) ? d_h1q[deg[ra0] & 1] : d_h2q[deg[ra0] & 1];
    const u32* h0b = (LAYER == 1) ? d_h1q[deg[ra1] & 1] : d_h2q[deg[ra1] & 1];
    const u32* p2a = h0a + (size_t)d_rank[ra0] * K2;
    const u32* p2b = h0b + (size_t)d_rank[ra1] * K2;
    const u32* q1a = W1 + (size_t)(n0 + prow) * K1;
    const u32* q2a = W2 + (size_t)(n0 + prow) * K2;
    const u32* q1b = W1 + (size_t)(n0 + ((prow + 64) & (BLKN - 1))) * K1;
    const u32* q2b = W2 + (size_t)(n0 + ((prow + 64) & (BLKN - 1))) * K2;

    const u32 a0s = smem_u32(&As[0][prow][c4]);
    const u32 a1s = a0s + 64 * 16 * 4;
    const u32 b0s = smem_u32(&Bs[0][prow & (BLKN - 1)][c4]);
    const u32 b1s = smem_u32(&Bs[0][(prow + 64) & (BLKN - 1)][c4]);

    float acc[4][NFRW][4];
#pragma unroll
    for (int i = 0; i < 4; i++)
#pragma unroll
        for (int j = 0; j < NFRW; j++)
#pragma unroll
            for (int c = 0; c < 4; c++) acc[i][j][c] = 0.f;

    auto gsel = [&](const u32* pk1, const u32* pk2, int kg) -> const u32* {
        return (kg < K1) ? (pk1 + kg) : (pk2 + (kg - K1));
    };
    auto issue = [&](int chunk) {
        if (chunk < NCH) {
            const int kg = chunk * 16 + c4;
            const int buf = chunk & 3;
            cpa16(a0s + buf * BUFSZ_A, gsel(p1a, p2a, kg));
            cpa16(a1s + buf * BUFSZ_A, gsel(p1b, p2b, kg));
            cpa16(b0s + buf * BUFSZ_B, gsel(q1a, q2a, kg));
            if (BLKN == 128) cpa16(b1s + buf * BUFSZ_B, gsel(q1b, q2b, kg));
        }
        cpa_commit();
    };
    issue(0); issue(1); issue(2);

#pragma unroll 1
    for (int c = 0; c < NCH; c++) {
        cpa_wait<2>();
        __syncthreads();
        issue(c + 3);
        mma_tile<NFRW>(As[c & 3], Bs[c & 3], acc, wm, wn, q, tig);
    }

    float2 bv2[NFRW];
#pragma unroll
    for (int nf = 0; nf < NFRW; nf++) {
        const int col = n0 + wn * (8 * NFRW) + nf * 8 + 2 * tig;
        bv2[nf] = make_float2(bias[col], bias[col + 1]);
    }
#pragma unroll
    for (int mf = 0; mf < 4; mf++)
#pragma unroll
        for (int half = 0; half < 2; half++) {
            const int r = r0 + wm * 64 + mf * 16 + q + half * 8;
            if (r >= n) continue;
#pragma unroll
            for (int nf = 0; nf < NFRW; nf++) {
                const int col = n0 + wn * (8 * NFRW) + nf * 8 + 2 * tig;
                float v0 = acc[mf][nf][half * 2]     + bv2[nf].x;
                float v1 = acc[mf][nf][half * 2 + 1] + bv2[nf].y;
                if (LAYER == 1) {
                    v0 = fmaxf(v0, 0.f); v1 = fmaxf(v1, 0.f);
                    const size_t hb = (size_t)r * NOUT + (col & ~15);
                    d_houtq[hb + PERM16(col & 15)]       = f2tf(v0);
                    d_houtq[hb + PERM16((col & 15) + 1)] = f2tf(v1);
                } else {
                    *(float2*)(outp + (size_t)r * NOUT + col) = make_float2(v0, v1);
                }
            }
        }
}

// ---------------- launch ----------------------------------------------------
extern "C" void kernel_launch(void* const* d_in, const int* in_sizes, int n_in,
                              void* d_out, int out_size)
{
    const float* feat    = (const float*)d_in[0];
    const int*   nbr     = (const int*)d_in[1];
    const int*   deg     = (const int*)d_in[2];
    const float* Wih1    = (const float*)d_in[3];
    const float* Whh1    = (const float*)d_in[4];
    const float* bih1    = (const float*)d_in[5];
    const float* bhh1    = (const float*)d_in[6];
    const float* Wself1  = (const float*)d_in[7];
    const float* Wneigh1 = (const float*)d_in[8];
    const float* b1      = (const float*)d_in[9];
    const float* Wih2    = (const float*)d_in[10];
    const float* Whh2    = (const float*)d_in[11];
    const float* bih2    = (const float*)d_in[12];
    const float* bhh2    = (const float*)d_in[13];
    const float* Wself2  = (const float*)d_in[14];
    const float* Wneigh2 = (const float*)d_in[15];
    const float* b2      = (const float*)d_in[16];

    const int n  = in_sizes[2];           // = N
    const int rb = (n + 127) / 128;

    sort_zero_k<<<1, 32>>>();
    sort_hist_k<<<(n + 255) / 256, 256>>>(deg, n);
    sort_scan_k<<<1, 1>>>();
    sort_scatter_k<<<(n + 255) / 256, 256>>>(deg, n);

    convert_all_k<<<1024, 256>>>(feat, in_sizes[0], Wih1, in_sizes[3],
                                 Whh1, in_sizes[4], Wih2, in_sizes[10],
                                 Whh2, in_sizes[11], Wself1, in_sizes[7],
                                 Wneigh1, in_sizes[8], Wself2, in_sizes[14],
                                 Wneigh2, in_sizes[15]);

    // layer 1
    mma_gx_k<128, 1><<<dim3(rb, 4), 256>>>(bih1, bhh1, n);
    for (int t = 0; t < 16; t++)
        mma_lstm_k<128, 1><<<dim3(rb, 4), 256>>>(nbr, t, n);
    mma_fc_k<128, 128, 256, 128, 1><<<dim3(rb, 2), 256>>>(deg, b1, nullptr, n);

    // layer 2
    mma_gx_k<256, 2><<<dim3(rb, 8), 256>>>(bih2, bhh2, n);
    for (int t = 0; t < 16; t++)
        mma_lstm_k<256, 2><<<dim3(rb, 8), 256>>>(nbr, t, n);
    mma_fc_k<256, 256, 64, 64, 2><<<dim3(rb, 1), 256>>>(deg, b2,
                                                        (float*)d_out, n);
}

// round 14
// speedup vs baseline: 1.8878x; 1.3390x over previous
#include <cuda_runtime.h>
#include <cuda_fp16.h>
#include <math.h>
#include <stdint.h>

#define NN    30000
#define DMAXN 16
#define INF   128
#define HIDF  256

typedef uint32_t u32;

// ---------------- fp16 / async helpers ---------------------------------------
// packed-word layout per 16-k chunk (8 u32 words): word w holds halves
//   w even: k = {w, w+1};  w odd: k = {w+7, w+8}
// so fragment words (2tig, 2tig+1) = k{2tig,2tig+1} and k{8+2tig,9+2tig}:
// one LDS.64 per fragment row.
__device__ __forceinline__ u32 packh2(float lo, float hi) {
    u32 r;
    asm("{ .reg .f16 l, h; cvt.rn.f16.f32 l, %1; cvt.rn.f16.f32 h, %2;"
        " mov.b32 %0, {l, h}; }" : "=r"(r) : "f"(lo), "f"(hi));
    return r;
}
__device__ __forceinline__ void mma16(float* d, u32 a0, u32 a1, u32 a2, u32 a3,
                                      u32 b0, u32 b1) {
    asm volatile("mma.sync.aligned.m16n8k16.row.col.f32.f16.f16.f32 "
                 "{%0,%1,%2,%3}, {%4,%5,%6,%7}, {%8,%9}, {%0,%1,%2,%3};"
                 : "+f"(d[0]), "+f"(d[1]), "+f"(d[2]), "+f"(d[3])
                 : "r"(a0), "r"(a1), "r"(a2), "r"(a3), "r"(b0), "r"(b1));
}
__device__ __forceinline__ u32 smem_u32(const void* p) {
    return (u32)__cvta_generic_to_shared(p);
}
__device__ __forceinline__ void cpa16(u32 d, const void* s) {
    asm volatile("cp.async.cg.shared.global [%0], [%1], 16;" :: "r"(d), "l"(s));
}
__device__ __forceinline__ void cpa_commit() {
    asm volatile("cp.async.commit_group;");
}
template <int N> __device__ __forceinline__ void cpa_wait() {
    asm volatile("cp.async.wait_group %0;" :: "n"(N));
}
__device__ __forceinline__ float sigmoid_f(float x) {
    return __fdividef(1.f, 1.f + __expf(-x));
}
__device__ __forceinline__ float tanh_f(float x) {
    float ax = fabsf(x);
    float e = __expf(-2.f * ax);
    return copysignf(__fdividef(1.f - e, 1.f + e), x);
}

// ---------------- scratch (device globals; fp16 packed = u32 words) ----------
__device__ u32   d_featq[NN * INF / 2];
__device__ u32   d_houtq[NN * HIDF / 2];
__device__ u32   d_h1q[2][NN * INF / 2];
__device__ u32   d_h2q[2][NN * HIDF / 2];
__device__ float d_c1[NN * INF];          // written at t=0 before any read
__device__ float d_c2[NN * HIDF];
__device__ float d_gx1[NN * 4 * INF];
__device__ float d_gx2[NN * 4 * HIDF];
__device__ u32   d_Wih1q[4 * INF * INF / 2];
__device__ u32   d_Whh1q[4 * INF * INF / 2];
__device__ u32   d_Wih2q[4 * HIDF * HIDF / 2];
__device__ u32   d_Whh2q[4 * HIDF * HIDF / 2];
__device__ u32   d_Ws1q[HIDF * INF / 2];
__device__ u32   d_Wn1q[HIDF * INF / 2];
__device__ u32   d_Ws2q[64 * HIDF / 2];
__device__ u32   d_Wn2q[64 * HIDF / 2];
__device__ int   d_perm[NN];
__device__ int   d_rank[NN];
__device__ int   d_cnt[DMAXN + 2];
__device__ int   d_ofs[DMAXN + 2];
__device__ int   d_Kt[DMAXN + 1];

// ---------------- counting sort by degree (descending) ----------------------
__global__ void sort_zero_k() {
    if (threadIdx.x < DMAXN + 2) d_cnt[threadIdx.x] = 0;
}
__global__ void sort_hist_k(const int* __restrict__ deg, int n) {
    int i = blockIdx.x * blockDim.x + threadIdx.x;
    if (i < n) atomicAdd(&d_cnt[deg[i]], 1);
}
__global__ void sort_scan_k() {
    int ofs[DMAXN + 2];
    int run = 0;
    for (int d = DMAXN; d >= 1; --d) { ofs[d] = run; run += d_cnt[d]; }
    for (int d = 1; d <= DMAXN; ++d) d_ofs[d] = ofs[d];
    for (int t = 0; t < DMAXN; ++t) d_Kt[t] = ofs[t + 1] + d_cnt[t + 1];
}
__global__ void sort_scatter_k(const int* __restrict__ deg, int n) {
    int i = blockIdx.x * blockDim.x + threadIdx.x;
    if (i < n) {
        int p = atomicAdd(&d_ofs[deg[i]], 1);
        d_perm[p] = i;
        d_rank[i] = p;
    }
}

// ---------------- fp32 -> fp16 packed-word layout, all operands --------------
__global__ void convert_all_k(const float* s0, int n0, const float* s1, int n1,
                              const float* s2, int n2, const float* s3, int n3,
                              const float* s4, int n4, const float* s5, int n5,
                              const float* s6, int n6, const float* s7, int n7,
                              const float* s8, int n8)
{
    const float* srcs[9] = {s0, s1, s2, s3, s4, s5, s6, s7, s8};
    u32* dsts[9] = {d_featq, d_Wih1q, d_Whh1q, d_Wih2q, d_Whh2q,
                    d_Ws1q, d_Wn1q, d_Ws2q, d_Wn2q};
    int lens[9] = {n0 / 2, n1 / 2, n2 / 2, n3 / 2, n4 / 2,
                   n5 / 2, n6 / 2, n7 / 2, n8 / 2};   // word counts
    int total = 0;
#pragma unroll
    for (int s = 0; s < 9; s++) total += lens[s];

    const int stride = gridDim.x * blockDim.x;
    for (int g = blockIdx.x * blockDim.x + threadIdx.x; g < total; g += stride) {
        int i = g, s = 0;
#pragma unroll
        for (int j = 0; j < 8; j++)
            if (i >= lens[s]) { i -= lens[s]; s++; }
        const int w = i & 7;
        const int k0 = (w & 1) ? (w + 7) : w;
        const int base = ((i >> 3) << 4) + k0;
        dsts[s][i] = packh2(srcs[s][base], srcs[s][base + 1]);
    }
}

// ---------------- shared mma tile: warp grid 2(M) x 4(N), fp16 k16 -----------
// smem rows: 8 u32 words (16 halves). LDS.64 fragments, conflict-free.
template <int NFRW>
__device__ __forceinline__ void mma_tile(const u32 (*__restrict__ As)[8],
                                         const u32 (*__restrict__ Bs)[8],
                                         float (*acc)[NFRW][4],
                                         int wm, int wn, int q, int tig)
{
    uint2 bv[NFRW];
#pragma unroll
    for (int nf = 0; nf < NFRW; nf++)
        bv[nf] = *(const uint2*)&Bs[wn * (8 * NFRW) + nf * 8 + q][2 * tig];
#pragma unroll
    for (int mf = 0; mf < 4; mf++) {
        const uint2 alo = *(const uint2*)&As[wm * 64 + mf * 16 + q][2 * tig];
        const uint2 ahi = *(const uint2*)&As[wm * 64 + mf * 16 + q + 8][2 * tig];
#pragma unroll
        for (int nf = 0; nf < NFRW; nf++)
            mma16(acc[mf][nf], alo.x, ahi.x, alo.y, ahi.y, bv[nf].x, bv[nf].y);
    }
}

// ============================================================================
// gx = A @ W^T + (bih+bhh) : A [n,K] fp16w, W [4K,K] fp16w, out fp32
// ============================================================================
template <int K, int SRC>
__global__ __launch_bounds__(256, 2)
void mma_gx_k(const float* __restrict__ bih, const float* __restrict__ bhh, int n)
{
    const int r0 = blockIdx.x * 128;
    if (r0 >= n) return;
    const int n0 = blockIdx.y * 128;
    constexpr int NCH = K / 16;
    constexpr int KW = K / 2;                 // words per row
    constexpr int M4 = 4 * K;

    __shared__ __align__(16) u32 As[4][128][8];
    __shared__ __align__(16) u32 Bs[4][128][8];
    constexpr u32 BUFSZ = 128 * 8 * 4;

    const u32* A  = (SRC == 1) ? d_featq : d_houtq;
    const u32* Wq = (SRC == 1) ? d_Wih1q : d_Wih2q;
    float* out    = (SRC == 1) ? d_gx1 : d_gx2;

    const int tid = threadIdx.x;
    const int w = tid >> 5, lane = tid & 31;
    const int q = lane >> 2, tig = lane & 3;
    const int wm = w >> 2, wn = w & 3;

    // cp.async mapping: one 16B segment per thread for A, one for B
    const int crow = tid >> 1;            // 0..127
    const int cseg = (tid & 1) * 4;       // word 0 or 4
    int ra = r0 + crow; if (ra > n - 1) ra = n - 1;
    const u32* pa = A + (size_t)ra * KW + cseg;
    const u32* pb = Wq + (size_t)(n0 + crow) * KW + cseg;

    const u32 asm0 = smem_u32(&As[0][crow][cseg]);
    const u32 bsm0 = smem_u32(&Bs[0][crow][cseg]);

    float acc[4][4][4];
#pragma unroll
    for (int i = 0; i < 4; i++)
#pragma unroll
        for (int j = 0; j < 4; j++)
#pragma unroll
            for (int c = 0; c < 4; c++) acc[i][j][c] = 0.f;

    auto issue = [&](int chunk) {
        if (chunk < NCH) {
            const u32 off = (chunk & 3) * BUFSZ;
            cpa16(asm0 + off, pa + chunk * 8);
            cpa16(bsm0 + off, pb + chunk * 8);
        }
        cpa_commit();
    };
    issue(0); issue(1); issue(2);

#pragma unroll 1
    for (int c = 0; c < NCH; c++) {
        cpa_wait<2>();
        __syncthreads();
        issue(c + 3);
        mma_tile<4>(As[c & 3], Bs[c & 3], acc, wm, wn, q, tig);
    }

    float2 bsum[4];
#pragma unroll
    for (int nf = 0; nf < 4; nf++) {
        const int col = n0 + wn * 32 + nf * 8 + 2 * tig;
        bsum[nf] = make_float2(bih[col] + bhh[col], bih[col + 1] + bhh[col + 1]);
    }
#pragma unroll
    for (int mf = 0; mf < 4; mf++)
#pragma unroll
        for (int half = 0; half < 2; half++) {
            const int r = r0 + wm * 64 + mf * 16 + q + half * 8;
            if (r >= n) continue;
#pragma unroll
            for (int nf = 0; nf < 4; nf++) {
                const int col = n0 + wn * 32 + nf * 8 + 2 * tig;
                *(float2*)(out + (size_t)r * M4 + col) =
                    make_float2(acc[mf][nf][half * 2]     + bsum[nf].x,
                                acc[mf][nf][half * 2 + 1] + bsum[nf].y);
            }
        }
}

// ============================================================================
// Fused LSTM step: gates = h_{t-1} @ Whh^T + gx[nbr] (biases folded into gx).
// B rows gate-regrouped: brow -> gate (brow>>3)&3, cell (brow&7)+8*(brow>>5).
// t==0: GEMM skipped AND c_old not read.
// ============================================================================
template <int H, int LAYER>
__global__ __launch_bounds__(256, 2)
void mma_lstm_k(const int* __restrict__ nbr_idx, int t, int n)
{
    const int Kt = d_Kt[t];
    const int r0 = blockIdx.x * 128;
    if (r0 >= Kt) return;
    const int j0 = blockIdx.y * 32;
    constexpr int NCH = H / 16;
    constexpr int HW = H / 2;

    __shared__ __align__(16) u32 As[4][128][8];
    __shared__ __align__(16) u32 Bs[4][128][8];
    __shared__ int s_nbr[128];
    constexpr u32 BUFSZ = 128 * 8 * 4;

    const float* gx  = (LAYER == 1) ? d_gx1 : d_gx2;
    const u32* hread = (LAYER == 1) ? d_h1q[t & 1] : d_h2q[t & 1];
    u32*      hwrite = (LAYER == 1) ? d_h1q[(t + 1) & 1] : d_h2q[(t + 1) & 1];
    float*    cst    = (LAYER == 1) ? d_c1 : d_c2;
    const u32* Wq    = (LAYER == 1) ? d_Whh1q : d_Whh2q;

    const int tid = threadIdx.x;
    const int w = tid >> 5, lane = tid & 31;
    const int q = lane >> 2, tig = lane & 3;
    const int wm = w >> 2, wn = w & 3;

    if (tid < 128) {
        int r = r0 + tid; if (r > Kt - 1) r = Kt - 1;
        s_nbr[tid] = nbr_idx[d_perm[r] * DMAXN + t];
    }

    float acc[4][4][4];
#pragma unroll
    for (int i = 0; i < 4; i++)
#pragma unroll
        for (int j = 0; j < 4; j++)
#pragma unroll
            for (int c = 0; c < 4; c++) acc[i][j][c] = 0.f;

    if (t > 0) {
        const int crow = tid >> 1;
        const int cseg = (tid & 1) * 4;
        int ra = r0 + crow; if (ra > n - 1) ra = n - 1;
        const u32* pa = hread + (size_t)ra * HW + cseg;
        const int brow = crow;
        const int wr = ((brow >> 3) & 3) * H + j0 + (brow & 7) + ((brow >> 5) << 3);
        const u32* pb = Wq + (size_t)wr * HW + cseg;

        const u32 asm0 = smem_u32(&As[0][crow][cseg]);
        const u32 bsm0 = smem_u32(&Bs[0][crow][cseg]);

        auto issue = [&](int chunk) {
            if (chunk < NCH) {
                const u32 off = (chunk & 3) * BUFSZ;
                cpa16(asm0 + off, pa + chunk * 8);
                cpa16(bsm0 + off, pb + chunk * 8);
            }
            cpa_commit();
        };
        issue(0); issue(1); issue(2);

#pragma unroll 1
        for (int c = 0; c < NCH; c++) {
            cpa_wait<2>();
            __syncthreads();
            issue(c + 3);
            mma_tile<4>(As[c & 3], Bs[c & 3], acc, wm, wn, q, tig);
        }
    }
    __syncthreads();

    // ---- fused cell update ----
    const int jc = j0 + wn * 8 + 2 * tig;
    const int jm = jc & 15;
    const int hw = (jm < 8) ? jm : jm - 7;            // packed word within chunk
    const int hwoff = ((jc >> 4) << 3) + hw;
#pragma unroll
    for (int mf = 0; mf < 4; mf++)
#pragma unroll
        for (int half = 0; half < 2; half++) {
            const int lr = wm * 64 + mf * 16 + q + half * 8;
            const int r = r0 + lr;
            if (r >= Kt) continue;
            const int nbr = s_nbr[lr];
            const float* gp = gx + (size_t)nbr * (4 * H) + jc;
            const float2 gI = *(const float2*)(gp);
            const float2 gF = *(const float2*)(gp + H);
            const float2 gG = *(const float2*)(gp + 2 * H);
            const float2 gO = *(const float2*)(gp + 3 * H);
            float2 cold = make_float2(0.f, 0.f);
            if (t > 0) cold = *(const float2*)(cst + (size_t)r * H + jc);
            float cn[2], hn[2];
#pragma unroll
            for (int b = 0; b < 2; b++) {
                const float gi = acc[mf][0][half * 2 + b] + (b ? gI.y : gI.x);
                const float gf = acc[mf][1][half * 2 + b] + (b ? gF.y : gF.x);
                const float gg = acc[mf][2][half * 2 + b] + (b ? gG.y : gG.x);
                const float go = acc[mf][3][half * 2 + b] + (b ? gO.y : gO.x);
                const float cv = sigmoid_f(gf) * (b ? cold.y : cold.x)
                               + sigmoid_f(gi) * tanh_f(gg);
                cn[b] = cv;
                hn[b] = sigmoid_f(go) * tanh_f(cv);
            }
            *(float2*)(cst + (size_t)r * H + jc) = make_float2(cn[0], cn[1]);
            hwrite[(size_t)r * HW + hwoff] = packh2(hn[0], hn[1]);
        }
}

// ============================================================================
// Fused FC: out = act(A1 @ W1^T + m @ W2^T + b), K = K1+K2 concat.
// LAYER 1 writes fp16-packed d_houtq (relu); LAYER 2 writes fp32 d_out.
// ============================================================================
template <int K1, int K2, int NOUT, int BLKN, int LAYER>
__global__ __launch_bounds__(256, 2)
void mma_fc_k(const int* __restrict__ deg, const float* __restrict__ bias,
              float* __restrict__ outp, int n)
{
    const int r0 = blockIdx.x * 128;
    if (r0 >= n) return;
    const int n0 = blockIdx.y * BLKN;
    constexpr int NCH = (K1 + K2) / 16;
    constexpr int NCH1 = K1 / 16;
    constexpr int NFRW = BLKN / 32;
    constexpr int K1W = K1 / 2, K2W = K2 / 2;

    __shared__ __align__(16) u32 As[4][128][8];
    __shared__ __align__(16) u32 Bs[4][BLKN][8];
    constexpr u32 BUFSZ_A = 128 * 8 * 4;
    constexpr u32 BUFSZ_B = BLKN * 8 * 4;

    const u32* A1 = (LAYER == 1) ? d_featq : d_houtq;
    const u32* W1 = (LAYER == 1) ? d_Ws1q : d_Ws2q;
    const u32* W2 = (LAYER == 1) ? d_Wn1q : d_Wn2q;

    const int tid = threadIdx.x;
    const int w = tid >> 5, lane = tid & 31;
    const int q = lane >> 2, tig = lane & 3;
    const int wm = w >> 2, wn = w & 3;

    const int crow = tid >> 1;
    const int cseg = (tid & 1) * 4;
    int ra = r0 + crow; if (ra > n - 1) ra = n - 1;
    const u32* p1 = A1 + (size_t)ra * K1W + cseg;
    const u32* hb = (LAYER == 1) ? d_h1q[deg[ra] & 1] : d_h2q[deg[ra] & 1];
    const u32* p2 = hb + (size_t)d_rank[ra] * K2W + cseg;
    const bool bact = (tid < 2 * BLKN);
    const int bro = n0 + (crow & (BLKN - 1));
    const u32* q1 = W1 + (size_t)bro * K1W + cseg;
    const u32* q2 = W2 + (size_t)bro * K2W + cseg;

    const u32 asm0 = smem_u32(&As[0][crow][cseg]);
    const u32 bsm0 = smem_u32(&Bs[0][crow & (BLKN - 1)][cseg]);

    float acc[4][NFRW][4];
#pragma unroll
    for (int i = 0; i < 4; i++)
#pragma unroll
        for (int j = 0; j < NFRW; j++)
#pragma unroll
            for (int c = 0; c < 4; c++) acc[i][j][c] = 0.f;

    auto issue = [&](int chunk) {
        if (chunk < NCH) {
            const u32 offA = (chunk & 3) * BUFSZ_A;
            const u32 offB = (chunk & 3) * BUFSZ_B;
            const u32* srcA = (chunk < NCH1) ? (p1 + chunk * 8)
                                             : (p2 + (chunk - NCH1) * 8);
            cpa16(asm0 + offA, srcA);
            if (bact) {
                const u32* srcB = (chunk < NCH1) ? (q1 + chunk * 8)
                                                 : (q2 + (chunk - NCH1) * 8);
                cpa16(bsm0 + offB, srcB);
            }
        }
        cpa_commit();
    };
    issue(0); issue(1); issue(2);

#pragma unroll 1
    for (int c = 0; c < NCH; c++) {
        cpa_wait<2>();
        __syncthreads();
        issue(c + 3);
        mma_tile<NFRW>(As[c & 3], Bs[c & 3], acc, wm, wn, q, tig);
    }

    float2 bv2[NFRW];
#pragma unroll
    for (int nf = 0; nf < NFRW; nf++) {
        const int col = n0 + wn * (8 * NFRW) + nf * 8 + 2 * tig;
        bv2[nf] = make_float2(bias[col], bias[col + 1]);
    }
#pragma unroll
    for (int mf = 0; mf < 4; mf++)
#pragma unroll
        for (int half = 0; half < 2; half++) {
            const int r = r0 + wm * 64 + mf * 16 + q + half * 8;
            if (r >= n) continue;
#pragma unroll
            for (int nf = 0; nf < NFRW; nf++) {
                const int col = n0 + wn * (8 * NFRW) + nf * 8 + 2 * tig;
                float v0 = acc[mf][nf][half * 2]     + bv2[nf].x;
                float v1 = acc[mf][nf][half * 2 + 1] + bv2[nf].y;
                if (LAYER == 1) {
                    v0 = fmaxf(v0, 0.f); v1 = fmaxf(v1, 0.f);
                    const int cm = col & 15;
                    const int cw = (cm < 8) ? cm : cm - 7;
                    d_houtq[(size_t)r * (NOUT / 2) + ((col >> 4) << 3) + cw] =
                        packh2(v0, v1);
                } else {
                    *(float2*)(outp + (size_t)r * NOUT + col) = make_float2(v0, v1);
                }
            }
        }
}

// ---------------- launch ----------------------------------------------------
extern "C" void kernel_launch(void* const* d_in, const int* in_sizes, int n_in,
                              void* d_out, int out_size)
{
    const float* feat    = (const float*)d_in[0];
    const int*   nbr     = (const int*)d_in[1];
    const int*   deg     = (const int*)d_in[2];
    const float* Wih1    = (const float*)d_in[3];
    const float* Whh1    = (const float*)d_in[4];
    const float* bih1    = (const float*)d_in[5];
    const float* bhh1    = (const float*)d_in[6];
    const float* Wself1  = (const float*)d_in[7];
    const float* Wneigh1 = (const float*)d_in[8];
    const float* b1      = (const float*)d_in[9];
    const float* Wih2    = (const float*)d_in[10];
    const float* Whh2    = (const float*)d_in[11];
    const float* bih2    = (const float*)d_in[12];
    const float* bhh2    = (const float*)d_in[13];
    const float* Wself2  = (const float*)d_in[14];
    const float* Wneigh2 = (const float*)d_in[15];
    const float* b2      = (const float*)d_in[16];

    const int n  = in_sizes[2];           // = N
    const int rb = (n + 127) / 128;

    sort_zero_k<<<1, 32>>>();
    sort_hist_k<<<(n + 255) / 256, 256>>>(deg, n);
    sort_scan_k<<<1, 1>>>();
    sort_scatter_k<<<(n + 255) / 256, 256>>>(deg, n);

    convert_all_k<<<1024, 256>>>(feat, in_sizes[0], Wih1, in_sizes[3],
                                 Whh1, in_sizes[4], Wih2, in_sizes[10],
                                 Whh2, in_sizes[11], Wself1, in_sizes[7],
                                 Wneigh1, in_sizes[8], Wself2, in_sizes[14],
                                 Wneigh2, in_sizes[15]);

    // layer 1
    mma_gx_k<128, 1><<<dim3(rb, 4), 256>>>(bih1, bhh1, n);
    for (int t = 0; t < 16; t++)
        mma_lstm_k<128, 1><<<dim3(rb, 4), 256>>>(nbr, t, n);
    mma_fc_k<128, 128, 256, 128, 1><<<dim3(rb, 2), 256>>>(deg, b1, nullptr, n);

    // layer 2
    mma_gx_k<256, 2><<<dim3(rb, 8), 256>>>(bih2, bhh2, n);
    for (int t = 0; t < 16; t++)
        mma_lstm_k<256, 2><<<dim3(rb, 8), 256>>>(nbr, t, n);
    mma_fc_k<256, 256, 64, 64, 2><<<dim3(rb, 1), 256>>>(deg, b2,
                                                        (float*)d_out, n);
}